// round 6
// baseline (speedup 1.0000x reference)
#include <cuda_runtime.h>
#include <math_constants.h>

#define NPTS 4096
#define WARPS_PER_BLOCK 28
#define NTHREADS (WARPS_PER_BLOCK * 32)      // 896
#define NBLOCKS 147                           // 147*28 = 4116 >= 4096, 1 block/SM
#define FULL 0xffffffffu
#define MARGIN 1e-2f

__device__ __forceinline__ void ins4(float dv, int j,
                                     float& d0, float& d1, float& d2, float& d3,
                                     int& i0, int& i1, int& i2, int& i3) {
    // warp-uniform insertion; calls arrive in strictly increasing j; strict '<'
    d3 = dv; i3 = j;
    if (d3 < d2) { float t=d3; d3=d2; d2=t; int u=i3; i3=i2; i2=u; }
    if (d2 < d1) { float t=d2; d2=d1; d1=t; int u=i2; i2=i1; i1=u; }
    if (d1 < d0) { float t=d1; d1=d0; d0=t; int u=i1; i1=i0; i0=u; }
}

// Check 4 broadcast screen values against treg; exact-recompute passers.
#define CHECK4(q0, q1, q2, q3, jb)                                             \
    do {                                                                       \
        if (q0 < treg) { int j = (jb);                                         \
            float dx = sx[j]-qx, dy = sy[j]-qy;                                \
            float dv = fmaf(dx,dx,fmaf(dy,dy,1.0f));                           \
            if (j != i && dv < d3) ins4(dv,j,d0,d1,d2,d3,i0,i1,i2,i3); }       \
        if (q1 < treg) { int j = (jb)+1;                                       \
            float dx = sx[j]-qx, dy = sy[j]-qy;                                \
            float dv = fmaf(dx,dx,fmaf(dy,dy,1.0f));                           \
            if (j != i && dv < d3) ins4(dv,j,d0,d1,d2,d3,i0,i1,i2,i3); }       \
        if (q2 < treg) { int j = (jb)+2;                                       \
            float dx = sx[j]-qx, dy = sy[j]-qy;                                \
            float dv = fmaf(dx,dx,fmaf(dy,dy,1.0f));                           \
            if (j != i && dv < d3) ins4(dv,j,d0,d1,d2,d3,i0,i1,i2,i3); }       \
        if (q3 < treg) { int j = (jb)+3;                                       \
            float dx = sx[j]-qx, dy = sy[j]-qy;                                \
            float dv = fmaf(dx,dx,fmaf(dy,dy,1.0f));                           \
            if (j != i && dv < d3) ins4(dv,j,d0,d1,d2,d3,i0,i1,i2,i3); }       \
        treg = d3 - qnm;                                                       \
    } while (0)

__global__ void __launch_bounds__(NTHREADS)
nn_tag_pool_kernel(const float2* __restrict__ obs1,
                   const float2* __restrict__ obs2,
                   const float*  __restrict__ W,
                   const float*  __restrict__ bias,
                   float* __restrict__ out)
{
    __shared__ __align__(16) float sx[NPTS];
    __shared__ __align__(16) float sy[NPTS];
    __shared__ __align__(16) float sn[NPTS];   // x^2 + y^2 + 1

    const int tid = threadIdx.x;
    {   // stage: deinterleave AoS -> SoA + precompute norms (float2 stores)
        const float4* g4 = (const float4*)obs2;
        float2* sx2 = (float2*)sx;
        float2* sy2 = (float2*)sy;
        float2* sn2 = (float2*)sn;
        for (int m = tid; m < NPTS / 2; m += NTHREADS) {
            float4 v = g4[m];                  // {x0,y0,x1,y1}
            sx2[m] = make_float2(v.x, v.z);
            sy2[m] = make_float2(v.y, v.w);
            sn2[m] = make_float2(fmaf(v.x, v.x, fmaf(v.y, v.y, 1.0f)),
                                 fmaf(v.z, v.z, fmaf(v.w, v.w, 1.0f)));
        }
    }
    __syncthreads();

    const int warp = tid >> 5;
    const int lane = tid & 31;
    const int i = blockIdx.x * WARPS_PER_BLOCK + warp;   // query row
    if (i >= NPTS) return;                    // whole tail warps only

    // fused-linear constants (lane = kk*8 + o); tag columns folded into bias
    const int o = lane & 7;
    const float w0 = W[o * 6 + 0];
    const float w1 = W[o * 6 + 1];
    const float w3 = W[o * 6 + 3];
    const float w4 = W[o * 6 + 4];
    const float cb = W[o * 6 + 2] + W[o * 6 + 5] + bias[o];

    const float qx = sx[i], qy = sy[i];
    const float qn  = fmaf(qx, qx, qy * qy);  // |q|^2
    const float qnm = qn - MARGIN;
    const float axc = -2.0f * qx, ayc = -2.0f * qy;

    // warp-uniform sorted top-4 (exact distances; ties -> smaller index)
    float d0 = CUDART_INF_F, d1 = CUDART_INF_F, d2 = CUDART_INF_F, d3 = CUDART_INF_F;
    int   i0 = 0, i1 = 0, i2 = 0, i3 = 0;
    float treg = CUDART_INF_F;                // = d3 - qnm (screen threshold, d' space)

    const float4* sx4 = (const float4*)sx;
    const float4* sy4 = (const float4*)sy;
    const float4* sn4 = (const float4*)sn;

    #pragma unroll 4
    for (int it = 0; it < NPTS / 256; ++it) { // 16 iters, 8 pts/lane, 256/warp
        const int m1 = it * 64 + lane;
        float4 XA = sx4[m1],      YA = sy4[m1],      NA = sn4[m1];
        float4 XB = sx4[m1 + 32], YB = sy4[m1 + 32], NB = sn4[m1 + 32];

        // screen value d' = (|p|^2+1) - 2 q.p = dist2 - |q|^2  (2 FFMA / point)
        float pa0 = fmaf(XA.x, axc, fmaf(YA.x, ayc, NA.x));
        float pa1 = fmaf(XA.y, axc, fmaf(YA.y, ayc, NA.y));
        float pa2 = fmaf(XA.z, axc, fmaf(YA.z, ayc, NA.z));
        float pa3 = fmaf(XA.w, axc, fmaf(YA.w, ayc, NA.w));
        float pb0 = fmaf(XB.x, axc, fmaf(YB.x, ayc, NB.x));
        float pb1 = fmaf(XB.y, axc, fmaf(YB.y, ayc, NB.y));
        float pb2 = fmaf(XB.z, axc, fmaf(YB.z, ayc, NB.z));
        float pb3 = fmaf(XB.w, axc, fmaf(YB.w, ayc, NB.w));

        float mna = fminf(fminf(pa0, pa1), fminf(pa2, pa3));
        float mnb = fminf(fminf(pb0, pb1), fminf(pb2, pb3));

        // pass A: points it*256 + [0,128)  (ascending j with ascending r)
        unsigned mk = __ballot_sync(FULL, mna < treg);
        while (mk) {                           // warp-uniform
            int r = __ffs(mk) - 1;
            mk &= mk - 1;
            float q0 = __shfl_sync(FULL, pa0, r);
            float q1 = __shfl_sync(FULL, pa1, r);
            float q2 = __shfl_sync(FULL, pa2, r);
            float q3 = __shfl_sync(FULL, pa3, r);
            CHECK4(q0, q1, q2, q3, (it * 64 + r) * 4);
            if (mk) mk &= __ballot_sync(FULL, mna < treg);   // refilter
        }
        // pass B: points it*256 + [128,256)
        mk = __ballot_sync(FULL, mnb < treg);
        while (mk) {
            int r = __ffs(mk) - 1;
            mk &= mk - 1;
            float q0 = __shfl_sync(FULL, pb0, r);
            float q1 = __shfl_sync(FULL, pb1, r);
            float q2 = __shfl_sync(FULL, pb2, r);
            float q3 = __shfl_sync(FULL, pb3, r);
            CHECK4(q0, q1, q2, q3, (it * 64 + 32 + r) * 4);
            if (mk) mk &= __ballot_sync(FULL, mnb < treg);
        }
    }

    // list is warp-uniform: lane kk*8+o computes channel o of neighbor kk
    const int kk = lane >> 3;
    const int j = (kk == 0) ? i0 : (kk == 1) ? i1 : (kk == 2) ? i2 : i3;

    const float pjx = sx[j], pjy = sy[j];
    const float2 a1j = obs1[j];
    const float2 a1i = obs1[i];

    const float px = pjx - qx;
    const float py = pjy - qy;
    const float vx = (pjx - a1j.x) - (qx - a1i.x);   // vel[j] - vel[i]
    const float vy = (pjy - a1j.y) - (qy - a1i.y);

    float r = fmaf(px, w0, fmaf(py, w1, fmaf(vx, w3, fmaf(vy, w4, cb))));
    out[i * 32 + lane] = fmaxf(r, 0.0f);
}

extern "C" void kernel_launch(void* const* d_in, const int* in_sizes, int n_in,
                              void* d_out, int out_size) {
    const float2* obs1 = (const float2*)d_in[0];
    const float2* obs2 = (const float2*)d_in[1];
    const float*  W    = (const float*)d_in[2];
    const float*  bias = (const float*)d_in[3];
    float* out = (float*)d_out;

    nn_tag_pool_kernel<<<NBLOCKS, NTHREADS>>>(obs1, obs2, W, bias, out);
}

// round 7
// speedup vs baseline: 1.3732x; 1.3732x over previous
#include <cuda_runtime.h>
#include <math_constants.h>

#define NPTS 4096
#define WARPS_PER_BLOCK 28
#define NTHREADS (WARPS_PER_BLOCK * 32)      // 896
#define NBLOCKS 147                           // 147*28 = 4116 >= 4096, 1 block/SM
#define FULL 0xffffffffu

__device__ __forceinline__ bool pless(float da, int ia, float db, int ib) {
    return (da < db) || (da == db && ia < ib);
}
#define CAS(dx, ix, dy, iy)                                  \
    do { if (!pless(dx, ix, dy, iy)) {                       \
        float _t = dx; dx = dy; dy = _t;                     \
        int _u = ix; ix = iy; iy = _u; } } while (0)

__device__ __forceinline__ void ins4(float dv, int j,
                                     float& d0, float& d1, float& d2, float& d3,
                                     int& i0, int& i1, int& i2, int& i3) {
    // calls arrive in strictly increasing j; strict '<' keeps top_k tie order
    d3 = dv; i3 = j;
    if (d3 < d2) { float t=d3; d3=d2; d2=t; int u=i3; i3=i2; i2=u; }
    if (d2 < d1) { float t=d2; d2=d1; d1=t; int u=i2; i2=i1; i1=u; }
    if (d1 < d0) { float t=d1; d1=d0; d0=t; int u=i1; i1=i0; i0=u; }
}

__global__ void __launch_bounds__(NTHREADS)
nn_tag_pool_kernel(const float2* __restrict__ obs1,
                   const float2* __restrict__ obs2,
                   const float*  __restrict__ W,
                   const float*  __restrict__ bias,
                   float* __restrict__ out)
{
    __shared__ __align__(16) float sx[NPTS];
    __shared__ __align__(16) float sy[NPTS];

    const int tid = threadIdx.x;
    {   // stage + deinterleave: obs2 AoS float2 -> SoA sx/sy
        const float4* g4 = (const float4*)obs2;
        for (int m = tid; m < NPTS / 2; m += NTHREADS) {
            float4 v = g4[m];                 // {x0,y0,x1,y1}
            sx[2*m]   = v.x;  sy[2*m]   = v.y;
            sx[2*m+1] = v.z;  sy[2*m+1] = v.w;
        }
    }
    __syncthreads();

    const int warp = tid >> 5;
    const int lane = tid & 31;
    const int i = blockIdx.x * WARPS_PER_BLOCK + warp;   // query row
    if (i >= NPTS) return;                    // whole tail warps only

    // fused-linear constants (lane = kk*8 + o); tag columns folded into bias
    const int o = lane & 7;
    const float w0 = W[o * 6 + 0];
    const float w1 = W[o * 6 + 1];
    const float w3 = W[o * 6 + 3];
    const float w4 = W[o * 6 + 4];
    const float cb = W[o * 6 + 2] + W[o * 6 + 5] + bias[o];

    const float qx = sx[i], qy = sy[i];

    const float4* sx4 = (const float4*)sx;
    const float4* sy4 = (const float4*)sy;

    // ---------- seed: exact top-4 of points [0,128), branch-free ----------
    float d0, d1, d2, d3;
    int   i0, i1, i2, i3;
    {
        float4 X = sx4[lane];
        float4 Y = sy4[lane];
        const int jb = 4 * lane;

        float dxa = X.x - qx, dya = Y.x - qy;
        float dxb = X.y - qx, dyb = Y.y - qy;
        float dxc = X.z - qx, dyc = Y.z - qy;
        float dxd = X.w - qx, dyd = Y.w - qy;
        float e0 = fmaf(dxa, dxa, fmaf(dya, dya, 1.0f)); int a0 = jb + 0;
        float e1 = fmaf(dxb, dxb, fmaf(dyb, dyb, 1.0f)); int a1 = jb + 1;
        float e2 = fmaf(dxc, dxc, fmaf(dyc, dyc, 1.0f)); int a2 = jb + 2;
        float e3 = fmaf(dxd, dxd, fmaf(dyd, dyd, 1.0f)); int a3 = jb + 3;
        if (a0 == i) { e0 = CUDART_INF_F; a0 = 0x7fffffff; }
        if (a1 == i) { e1 = CUDART_INF_F; a1 = 0x7fffffff; }
        if (a2 == i) { e2 = CUDART_INF_F; a2 = 0x7fffffff; }
        if (a3 == i) { e3 = CUDART_INF_F; a3 = 0x7fffffff; }

        // sort 4 under (dist, idx) total order: 5-CAS network
        CAS(e0, a0, e2, a2); CAS(e1, a1, e3, a3);
        CAS(e0, a0, e1, a1); CAS(e2, a2, e3, a3);
        CAS(e1, a1, e2, a2);
        d0 = e0; d1 = e1; d2 = e2; d3 = e3;
        i0 = a0; i1 = a1; i2 = a2; i3 = a3;

        // butterfly merge: 32 sorted-4 -> warp-uniform global sorted-4
        #pragma unroll
        for (int off = 16; off >= 1; off >>= 1) {
            float f0 = __shfl_xor_sync(FULL, d0, off);
            float f1 = __shfl_xor_sync(FULL, d1, off);
            float f2 = __shfl_xor_sync(FULL, d2, off);
            float f3 = __shfl_xor_sync(FULL, d3, off);
            int   g0 = __shfl_xor_sync(FULL, i0, off);
            int   g1 = __shfl_xor_sync(FULL, i1, off);
            int   g2 = __shfl_xor_sync(FULL, i2, off);
            int   g3 = __shfl_xor_sync(FULL, i3, off);

            float m0, m1, m2, m3; int n0, n1, n2, n3;
            if (pless(d0, i0, f3, g3)) { m0 = d0; n0 = i0; } else { m0 = f3; n0 = g3; }
            if (pless(d1, i1, f2, g2)) { m1 = d1; n1 = i1; } else { m1 = f2; n1 = g2; }
            if (pless(d2, i2, f1, g1)) { m2 = d2; n2 = i2; } else { m2 = f1; n2 = g1; }
            if (pless(d3, i3, f0, g0)) { m3 = d3; n3 = i3; } else { m3 = f0; n3 = g0; }

            CAS(m0, n0, m2, n2); CAS(m1, n1, m3, n3);
            CAS(m0, n0, m1, n1); CAS(m2, n2, m3, n3);

            d0 = m0; d1 = m1; d2 = m2; d3 = m3;
            i0 = n0; i1 = n1; i2 = n2; i3 = n3;
        }
    }
    // d0..d3 / i0..i3 now warp-uniform exact top-4 of prefix [0,128)

    // ---------- main scan: iters 1..31, ballot-gated rare slow path ----------
    #pragma unroll 4
    for (int it = 1; it < NPTS / 128; ++it) { // 4 pts/lane, 128/warp
        float4 X = sx4[it * 32 + lane];
        float4 Y = sy4[it * 32 + lane];

        float dxa = X.x - qx, dya = Y.x - qy;
        float dxb = X.y - qx, dyb = Y.y - qy;
        float dxc = X.z - qx, dyc = Y.z - qy;
        float dxd = X.w - qx, dyd = Y.w - qy;
        float v0 = fmaf(dxa, dxa, fmaf(dya, dya, 1.0f));
        float v1 = fmaf(dxb, dxb, fmaf(dyb, dyb, 1.0f));
        float v2 = fmaf(dxc, dxc, fmaf(dyc, dyc, 1.0f));
        float v3 = fmaf(dxd, dxd, fmaf(dyd, dyd, 1.0f));
        float mn = fminf(fminf(v0, v1), fminf(v2, v3));

        unsigned m = __ballot_sync(FULL, mn < d3);
        while (m) {                            // warp-uniform (m uniform), rare
            int r = __ffs(m) - 1;
            m &= m - 1;
            float x0 = __shfl_sync(FULL, v0, r);
            float x1 = __shfl_sync(FULL, v1, r);
            float x2 = __shfl_sync(FULL, v2, r);
            float x3 = __shfl_sync(FULL, v3, r);
            int jb = (it * 32 + r) * 4;        // candidates jb..jb+3, ascending

            if (jb + 0 != i && x0 < d3) ins4(x0, jb + 0, d0,d1,d2,d3, i0,i1,i2,i3);
            if (jb + 1 != i && x1 < d3) ins4(x1, jb + 1, d0,d1,d2,d3, i0,i1,i2,i3);
            if (jb + 2 != i && x2 < d3) ins4(x2, jb + 2, d0,d1,d2,d3, i0,i1,i2,i3);
            if (jb + 3 != i && x3 < d3) ins4(x3, jb + 3, d0,d1,d2,d3, i0,i1,i2,i3);

            if (m) m &= __ballot_sync(FULL, mn < d3);  // refilter vs tighter d3
        }
    }

    // ---------- epilogue: lane kk*8+o -> channel o of neighbor kk ----------
    const int kk = lane >> 3;
    const int j = (kk == 0) ? i0 : (kk == 1) ? i1 : (kk == 2) ? i2 : i3;

    const float pjx = sx[j], pjy = sy[j];
    const float2 a1j = obs1[j];
    const float2 a1i = obs1[i];

    const float px = pjx - qx;
    const float py = pjy - qy;
    const float vx = (pjx - a1j.x) - (qx - a1i.x);   // vel[j] - vel[i]
    const float vy = (pjy - a1j.y) - (qy - a1i.y);

    float r = fmaf(px, w0, fmaf(py, w1, fmaf(vx, w3, fmaf(vy, w4, cb))));
    out[i * 32 + lane] = fmaxf(r, 0.0f);
}

extern "C" void kernel_launch(void* const* d_in, const int* in_sizes, int n_in,
                              void* d_out, int out_size) {
    const float2* obs1 = (const float2*)d_in[0];
    const float2* obs2 = (const float2*)d_in[1];
    const float*  W    = (const float*)d_in[2];
    const float*  bias = (const float*)d_in[3];
    float* out = (float*)d_out;

    nn_tag_pool_kernel<<<NBLOCKS, NTHREADS>>>(obs1, obs2, W, bias, out);
}